// round 6
// baseline (speedup 1.0000x reference)
#include <cuda_runtime.h>

// out[b, q, dv] = (1/SK) * sum_k value[b, k, dv]
// (q and k are the same broadcast scalar -> all logits equal -> softmax uniform
//  -> output = mean of value over SK, independent of query and q_param.)
//
// Single fused kernel: per-batch split reduce -> device spin barrier ->
// combine -> broadcast stores. Counters self-reset (graph-replay safe).

#define B   16
#define SQ  2048
#define SK  2048
#define DV  128
#define SPB 32                     // blocks (splits) per batch
#define RPB (SK / SPB)             // 64 rows per block

__device__ float4 g_part[B * SPB * 32];  // per-(b,split) partial row
__device__ int    g_cnt[B];              // arrivals  (zero-init, self-reset)
__device__ int    g_done[B];             // finishers (zero-init, self-reset)

__global__ void __launch_bounds__(256, 4)
fused_kernel(const float4* __restrict__ value, float4* __restrict__ out) {
    const int b   = blockIdx.y;
    const int sp  = blockIdx.x;          // 0..31
    const int tid = threadIdx.x;
    const int dv4 = tid & 31;            // float4 column
    const int rg  = tid >> 5;            // 0..7

    __shared__ float4 tmp[256];
    __shared__ float4 fin[32];

    // ---- Phase A: partial reduce of rows [sp*64, sp*64+64) ----
    const float4* base = value + ((size_t)b * SK + sp * RPB + rg) * (DV / 4) + dv4;
    float4 s = make_float4(0.f, 0.f, 0.f, 0.f);
    #pragma unroll
    for (int k = 0; k < RPB / 8; ++k) {
        float4 v = base[(size_t)k * 8 * (DV / 4)];
        s.x += v.x; s.y += v.y; s.z += v.z; s.w += v.w;
    }
    tmp[tid] = s;
    __syncthreads();

    if (tid < 32) {
        float4 a = tmp[tid];
        #pragma unroll
        for (int g = 1; g < 8; ++g) {
            float4 v = tmp[g * 32 + tid];
            a.x += v.x; a.y += v.y; a.z += v.z; a.w += v.w;
        }
        g_part[(b * SPB + sp) * 32 + tid] = a;
    }

    // ---- Device barrier over the 32 blocks of this batch ----
    if (tid == 0) {
        __threadfence();                       // publish g_part
        atomicAdd(&g_cnt[b], 1);
        int c;
        do {
            asm volatile("ld.acquire.gpu.global.s32 %0, [%1];"
                         : "=r"(c) : "l"(&g_cnt[b]) : "memory");
            if (c < SPB) __nanosleep(64);
        } while (c < SPB);
    }
    __syncthreads();

    // ---- Phase B: combine 32 partials -> final scaled row ----
    {
        const int sg = tid >> 5;               // 8 groups of 4 splits
        float4 a = make_float4(0.f, 0.f, 0.f, 0.f);
        #pragma unroll
        for (int spp = sg * 4; spp < sg * 4 + 4; ++spp) {
            float4 v = g_part[(b * SPB + spp) * 32 + dv4];
            a.x += v.x; a.y += v.y; a.z += v.z; a.w += v.w;
        }
        tmp[tid] = a;
    }
    __syncthreads();
    if (tid < 32) {
        const float inv = 1.0f / (float)SK;
        float4 a = tmp[tid];
        #pragma unroll
        for (int g = 1; g < 8; ++g) {
            float4 v = tmp[g * 32 + tid];
            a.x += v.x; a.y += v.y; a.z += v.z; a.w += v.w;
        }
        a.x *= inv; a.y *= inv; a.z *= inv; a.w *= inv;
        fin[tid] = a;
    }
    __syncthreads();

    // ---- Phase C: broadcast to rows [sp*64, sp*64+64) ----
    {
        const float4 v = fin[dv4];
        float4* o = out + ((size_t)b * SQ + sp * RPB + rg) * (DV / 4) + dv4;
        #pragma unroll
        for (int i = 0; i < 8; ++i) {
            o[(size_t)i * 8 * (DV / 4)] = v;
        }
    }

    // ---- Self-reset counters (last finisher per batch) ----
    if (tid == 0) {
        int d = atomicAdd(&g_done[b], 1);
        if (d == SPB - 1) {
            g_done[b] = 0;
            g_cnt[b]  = 0;
        }
    }
}

extern "C" void kernel_launch(void* const* d_in, const int* in_sizes, int n_in,
                              void* d_out, int out_size) {
    // inputs: query[B,SQ,D], key[B,SK,D], value[B,SK,DV], q_param[1,1]
    const float4* value = (const float4*)d_in[2];
    float4* out = (float4*)d_out;

    dim3 grid(SPB, B);
    fused_kernel<<<grid, 256>>>(value, out);
}